// round 14
// baseline (speedup 1.0000x reference)
#include <cuda_runtime.h>

typedef unsigned long long ull;

#define THREADS 128
#define NWARP 4
#define SEQ 512
#define DIN 120
#define NJ 25
#define NC 5
#define ROUTINGS 4
#define WROW 28          // padded W row in constant mem (112B, 16B-aligned)
#define CK 20            // k-chunk width
#define NCHK 6           // 120 / 20
#define SSTR 20          // x slab row stride (floats); lanes 80B apart -> bank-distinct
#define WRPW 128         // rows per warp (4 per thread)
#define SLABF (WRPW * SSTR)   // 2560 floats per buffer

// shared layout (floats): 4 warps x 2 x-buffers, then routing scratch
#define SM_X    0
#define SM_RED  (NWARP * 2 * SLABF)       // 20480
#define SM_SFIN (SM_RED + NWARP * 26)     // 20584
#define SM_TOTF (SM_SFIN + 32)            // 20616 floats = 82464 B

__constant__ float Wc[DIN * WROW];

__device__ __forceinline__ ull ffma2(ull a, ull b, ull c) {
    ull d;
    asm("fma.rn.f32x2 %0, %1, %2, %3;" : "=l"(d) : "l"(a), "l"(b), "l"(c));
    return d;
}
__device__ __forceinline__ ull pack2(float lo, float hi) {
    ull r; asm("mov.b64 %0, {%1, %2};" : "=l"(r) : "f"(lo), "f"(hi)); return r;
}
__device__ __forceinline__ void unpack2(ull v, float& lo, float& hi) {
    asm("mov.b64 {%0, %1}, %2;" : "=f"(lo), "=f"(hi) : "l"(v));
}

// stage one CK-column chunk of this warp's 128 rows into buf (coalesced cp.async)
__device__ __forceinline__ void stage_chunk(const float* __restrict__ xw, int k0,
                                            float* __restrict__ buf, int lane)
{
    #pragma unroll
    for (int m = 0; m < 20; ++m) {
        int idx = lane + 32 * m;          // 0..639 = 128 rows x 5 segs
        int row = idx / 5;
        int seg = idx - row * 5;
        const float* g = xw + row * DIN + k0 + seg * 4;   // 16B-aligned
        unsigned s = (unsigned)__cvta_generic_to_shared(buf + row * SSTR + seg * 4);
        asm volatile("cp.async.cg.shared.global [%0], [%1], 16;" :: "r"(s), "l"(g));
    }
    asm volatile("cp.async.commit_group;");
}

__global__ __launch_bounds__(THREADS, 2)
void caps_kernel(const float* __restrict__ x, float* __restrict__ out)
{
    extern __shared__ float sm[];
    float* red  = sm + SM_RED;
    float* sfin = sm + SM_SFIN;

    const int tid  = threadIdx.x;
    const int wid  = tid >> 5;
    const int lane = tid & 31;
    const int bb   = blockIdx.x;
    const float* xb = x + (size_t)bb * (SEQ * DIN);
    const float* xw = xb + (wid * WRPW) * DIN;     // warp's 128-row window
    float* slabA = sm + SM_X + (wid * 2 + 0) * SLABF;
    float* slabB = sm + SM_X + (wid * 2 + 1) * SLABF;

    // thread owns 4 rows: wid*128 + lane + {0,32,64,96}
    ull acc[4][13];
    #pragma unroll
    for (int m = 0; m < 4; ++m)
        #pragma unroll
        for (int t = 0; t < 13; ++t) acc[m][t] = 0ull;

    stage_chunk(xw, 0, slabA, lane);

    for (int c = 0; c < NCHK; ++c) {
        float* cur = (c & 1) ? slabB : slabA;
        float* nxt = (c & 1) ? slabA : slabB;
        if (c + 1 < NCHK) {
            stage_chunk(xw, (c + 1) * CK, nxt, lane);
            asm volatile("cp.async.wait_group 1;");
        } else {
            asm volatile("cp.async.wait_group 0;");
        }
        __syncwarp();

        const int k0 = c * CK;
        const float* r0 = cur + lane * SSTR;   // rows lane+32m at +2560m floats

        #pragma unroll 4
        for (int kk = 0; kk < CK; ++kk) {
            // 4 scalar LDS, lanes bank-distinct (80B apart), rows 10KB apart
            ull xp[4];
            #pragma unroll
            for (int m = 0; m < 4; ++m) {
                float xv = r0[m * 32 * SSTR + kk];
                xp[m] = pack2(xv, xv);
            }
            const double2* wr = (const double2*)(Wc + (k0 + kk) * WROW);
            #pragma unroll
            for (int t = 0; t < 7; ++t) {
                double2 w = wr[t];                    // constant-port 16B load
                ull wlo = __double_as_longlong(w.x);
                #pragma unroll
                for (int m = 0; m < 4; ++m)
                    acc[m][2 * t] = ffma2(xp[m], wlo, acc[m][2 * t]);
                if (t < 6) {
                    ull whi = __double_as_longlong(w.y);
                    #pragma unroll
                    for (int m = 0; m < 4; ++m)
                        acc[m][2 * t + 1] = ffma2(xp[m], whi, acc[m][2 * t + 1]);
                }
            }
        }
        __syncwarp();   // all lanes done reading cur before it is re-staged
    }

    // accumulators become routing-resident u_hat rows (4 rows x 26, col 25 = pad)
    float u[4][26];
    #pragma unroll
    for (int m = 0; m < 4; ++m)
        #pragma unroll
        for (int t = 0; t < 13; ++t)
            unpack2(acc[m][t], u[m][2 * t], u[m][2 * t + 1]);

    // ================= dynamic routing (4 iterations) =================
    float l[4][NC];
    #pragma unroll
    for (int m = 0; m < 4; ++m)
        #pragma unroll
        for (int i = 0; i < NC; ++i) l[m][i] = 0.f;

    for (int it = 0; it < ROUTINGS; ++it) {
        // softmax over the capsule axis (5) for each of the 4 owned rows
        float cw[4][NC];
        #pragma unroll
        for (int m = 0; m < 4; ++m) {
            float mx = l[m][0];
            #pragma unroll
            for (int i = 1; i < NC; ++i) mx = fmaxf(mx, l[m][i]);
            float s = 0.f;
            #pragma unroll
            for (int i = 0; i < NC; ++i) { cw[m][i] = __expf(l[m][i] - mx); s += cw[m][i]; }
            float r = __fdividef(1.f, s);
            #pragma unroll
            for (int i = 0; i < NC; ++i) cw[m][i] *= r;
        }

        // partial s[i][k] over this thread's four rows
        float part[NJ];
        #pragma unroll
        for (int i = 0; i < NC; ++i)
            #pragma unroll
            for (int k = 0; k < NC; ++k) {
                float p = cw[0][i] * u[0][i * NC + k];
                p += cw[1][i] * u[1][i * NC + k];
                p += cw[2][i] * u[2][i * NC + k];
                p += cw[3][i] * u[3][i * NC + k];
                part[i * NC + k] = p;
            }

        // block reduce 25 values over 128 threads
        #pragma unroll
        for (int v = 0; v < NJ; ++v) {
            part[v] += __shfl_xor_sync(0xffffffffu, part[v], 16);
            part[v] += __shfl_xor_sync(0xffffffffu, part[v], 8);
            part[v] += __shfl_xor_sync(0xffffffffu, part[v], 4);
            part[v] += __shfl_xor_sync(0xffffffffu, part[v], 2);
            part[v] += __shfl_xor_sync(0xffffffffu, part[v], 1);
        }
        if (lane == 0) {
            #pragma unroll
            for (int v = 0; v < NJ; ++v) red[wid * 26 + v] = part[v];
        }
        __syncthreads();
        if (tid < NJ) {
            float a = red[tid] + red[26 + tid] + red[52 + tid] + red[78 + tid];
            sfin[tid] = a;
        }
        __syncthreads();

        // squash scale per capsule (broadcast read from smem)
        float inv[NC];
        #pragma unroll
        for (int i = 0; i < NC; ++i) {
            float n2 = 1e-7f;
            #pragma unroll
            for (int k = 0; k < NC; ++k) {
                float sv = sfin[i * NC + k];
                n2 += sv * sv;
            }
            inv[i] = rsqrtf(n2);
        }

        if (it < ROUTINGS - 1) {
            // b[i][j] = sum_k outputs[i][k] * u[i][j][k]   (replace, per reference)
            #pragma unroll
            for (int i = 0; i < NC; ++i) {
                float d0 = 0.f, d1 = 0.f, d2 = 0.f, d3 = 0.f;
                #pragma unroll
                for (int k = 0; k < NC; ++k) {
                    float o = sfin[i * NC + k] * inv[i];
                    d0 += o * u[0][i * NC + k];
                    d1 += o * u[1][i * NC + k];
                    d2 += o * u[2][i * NC + k];
                    d3 += o * u[3][i * NC + k];
                }
                l[0][i] = d0; l[1][i] = d1; l[2][i] = d2; l[3][i] = d3;
            }
        } else {
            if (tid < NJ) out[bb * NJ + tid] = sfin[tid] * inv[tid / NC];
        }
    }
}

extern "C" void kernel_launch(void* const* d_in, const int* in_sizes, int n_in,
                              void* d_out, int out_size) {
    const float* x = (const float*)d_in[0];
    const float* W = (const float*)d_in[1];
    float* out = (float*)d_out;
    int batch = in_sizes[0] / (SEQ * DIN);

    // constant W, padded 28-float rows (pad cols stay zero)
    void* wcAddr = nullptr;
    cudaGetSymbolAddress(&wcAddr, Wc);
    cudaMemcpy2DAsync(wcAddr, WROW * sizeof(float),
                      W, NJ * sizeof(float),
                      NJ * sizeof(float), DIN,
                      cudaMemcpyDeviceToDevice);

    cudaFuncSetAttribute(caps_kernel, cudaFuncAttributeMaxDynamicSharedMemorySize,
                         SM_TOTF * (int)sizeof(float));
    caps_kernel<<<batch, THREADS, SM_TOTF * (int)sizeof(float)>>>(x, out);
}